// round 2
// baseline (speedup 1.0000x reference)
#include <cuda_runtime.h>
#include <math.h>

// Problem constants
#define NN      50000          // nodes
#define NE      512000         // edges
#define NRELS   8
#define DIMF    256            // DIM == HID
#define NQ      32
#define KENT    50
#define NSEL    (NQ + NQ*KENT) // 1632
#define ADAPTD  1024
#define OUTD    4096

// -------- device scratch (static, no allocs) --------
__device__ float g_base[(size_t)NN * DIMF];                 // 51.2 MB
__device__ float g_T   [(size_t)NRELS * NN * DIMF];         // 409.6 MB
__device__ float g_h   [(size_t)NN * DIMF];                 // 51.2 MB
__device__ float g_upd [(size_t)NN * DIMF];                 // 51.2 MB
__device__ float g_selin[(size_t)NSEL * 2 * DIMF];          // 3.3 MB
__device__ float g_hid  [(size_t)NSEL * ADAPTD];            // 6.7 MB

// -------- gather base = emb_table[node_ids] --------
__global__ void gather_base_kernel(const float* __restrict__ emb,
                                   const int* __restrict__ node_ids)
{
    int t = blockIdx.x * blockDim.x + threadIdx.x;     // one float4 per thread
    int total = NN * (DIMF / 4);
    if (t >= total) return;
    int row = t >> 6;            // /64 float4s per row
    int c4  = t & 63;
    int id = __ldg(node_ids + row);
    float4 v = __ldg((const float4*)(emb + (size_t)id * DIMF) + c4);
    *((float4*)(g_base + (size_t)row * DIMF) + c4) = v;
}

// -------- generic SGEMM: C[z] = A @ B[z] (+bias)(+act) --------
// A: M x K row-major, B: K x N row-major, C: M x N row-major
// BM=BN=64, BK=16, 256 threads, 4x4 per thread.
// Requires: N % 64 == 0, K % 16 == 0. M arbitrary.
// ACT: 0 = none, 2 = silu
template<int ACT>
__global__ void __launch_bounds__(256)
sgemm_kernel(const float* __restrict__ A,
             const float* __restrict__ B,
             float* __restrict__ C,
             const float* __restrict__ bias,
             int M, int N, int K,
             long long strideB, long long strideC)
{
    const int z = blockIdx.z;
    B += (long long)z * strideB;
    C += (long long)z * strideC;

    __shared__ float As[16][64];   // [k][m]
    __shared__ float Bs[16][64];   // [k][n]

    const int tid  = threadIdx.x;          // 0..255
    const int tr   = tid >> 4;             // 0..15 (row group)
    const int tc   = tid & 15;             // 0..15 (col group)
    const int row0 = blockIdx.y * 64;
    const int col0 = blockIdx.x * 64;

    // load mapping
    const int a_row  = tid >> 2;           // 0..63
    const int a_col4 = (tid & 3) << 2;     // 0,4,8,12
    const int b_row  = tid >> 4;           // 0..15
    const int b_col4 = (tid & 15) << 2;    // 0..60

    float acc[4][4] = {{0.f}};

    for (int k0 = 0; k0 < K; k0 += 16) {
        // A tile 64x16 -> transposed staging
        float4 av = make_float4(0.f, 0.f, 0.f, 0.f);
        int gr = row0 + a_row;
        if (gr < M)
            av = *(const float4*)(A + (long long)gr * K + k0 + a_col4);
        As[a_col4 + 0][a_row] = av.x;
        As[a_col4 + 1][a_row] = av.y;
        As[a_col4 + 2][a_row] = av.z;
        As[a_col4 + 3][a_row] = av.w;
        // B tile 16x64
        float4 bv = *(const float4*)(B + (long long)(k0 + b_row) * N + col0 + b_col4);
        *(float4*)&Bs[b_row][b_col4] = bv;
        __syncthreads();

        #pragma unroll
        for (int k = 0; k < 16; ++k) {
            float4 a = *(const float4*)&As[k][tr << 2];
            float4 b = *(const float4*)&Bs[k][tc << 2];
            acc[0][0] += a.x * b.x; acc[0][1] += a.x * b.y;
            acc[0][2] += a.x * b.z; acc[0][3] += a.x * b.w;
            acc[1][0] += a.y * b.x; acc[1][1] += a.y * b.y;
            acc[1][2] += a.y * b.z; acc[1][3] += a.y * b.w;
            acc[2][0] += a.z * b.x; acc[2][1] += a.z * b.y;
            acc[2][2] += a.z * b.z; acc[2][3] += a.z * b.w;
            acc[3][0] += a.w * b.x; acc[3][1] += a.w * b.y;
            acc[3][2] += a.w * b.z; acc[3][3] += a.w * b.w;
        }
        __syncthreads();
    }

    const int colb = col0 + (tc << 2);
    float4 bb = make_float4(0.f, 0.f, 0.f, 0.f);
    if (bias) bb = *(const float4*)(bias + colb);

    #pragma unroll
    for (int i = 0; i < 4; ++i) {
        int gr = row0 + (tr << 2) + i;
        if (gr >= M) continue;
        float4 r;
        r.x = acc[i][0] + bb.x;
        r.y = acc[i][1] + bb.y;
        r.z = acc[i][2] + bb.z;
        r.w = acc[i][3] + bb.w;
        if (ACT == 2) {   // silu
            r.x = r.x / (1.f + expf(-r.x));
            r.y = r.y / (1.f + expf(-r.y));
            r.z = r.z / (1.f + expf(-r.z));
            r.w = r.w / (1.f + expf(-r.w));
        }
        *(float4*)(C + (long long)gr * N + colb) = r;
    }
}

// -------- edge scatter: out[dst] += T[etype, src] --------
// 256 threads = 4 edges/block, 64 lanes x float4 per edge.
// Uses red.global.add.v4.f32 (sm_90+) -> 1 reduction op per 16 bytes.
__global__ void edge_scatter_kernel(const int* __restrict__ src,
                                    const int* __restrict__ dst,
                                    const int* __restrict__ et,
                                    const float* __restrict__ T,
                                    float* __restrict__ out)
{
    int e = blockIdx.x * 4 + (threadIdx.x >> 6);
    if (e >= NE) return;
    int lane = threadIdx.x & 63;
    int s = __ldg(src + e);
    int d = __ldg(dst + e);
    int r = __ldg(et + e);
    float4 v = __ldg((const float4*)(T + ((size_t)r * NN + s) * DIMF) + lane);
    float* o = out + (size_t)d * DIMF + (lane << 2);
    asm volatile("red.global.add.v4.f32 [%0], {%1, %2, %3, %4};"
                 :: "l"(o), "f"(v.x), "f"(v.y), "f"(v.z), "f"(v.w)
                 : "memory");
}

// -------- in-place relu on g_h --------
__global__ void relu_kernel(float* __restrict__ x, int n4)
{
    int t = blockIdx.x * blockDim.x + threadIdx.x;
    if (t >= n4) return;
    float4 v = ((float4*)x)[t];
    v.x = fmaxf(v.x, 0.f); v.y = fmaxf(v.y, 0.f);
    v.z = fmaxf(v.z, 0.f); v.w = fmaxf(v.w, 0.f);
    ((float4*)x)[t] = v;
}

// -------- gather selected rows: [base | upd] for queries then entities --------
__global__ void sel_gather_kernel(const int* __restrict__ qidx,
                                  const int* __restrict__ eidx)
{
    int t = blockIdx.x * blockDim.x + threadIdx.x;   // one float4
    int total = NSEL * (2 * DIMF / 4);               // 1632 * 128
    if (t >= total) return;
    int row = t >> 7;          // /128
    int c4  = t & 127;
    int id = (row < NQ) ? __ldg(qidx + row) : __ldg(eidx + row - NQ);
    float4 v;
    if (c4 < 64)
        v = __ldg((const float4*)(g_base + (size_t)id * DIMF) + c4);
    else
        v = __ldg((const float4*)(g_upd + (size_t)id * DIMF) + (c4 - 64));
    *((float4*)(g_selin + (size_t)row * 2 * DIMF) + c4) = v;
}

extern "C" void kernel_launch(void* const* d_in, const int* in_sizes, int n_in,
                              void* d_out, int out_size)
{
    const int*   qidx    = (const int*)  d_in[0];
    const int*   eidx    = (const int*)  d_in[1];
    const int*   nids    = (const int*)  d_in[2];
    const int*   src     = (const int*)  d_in[3];
    const int*   dst     = (const int*)  d_in[4];
    const int*   etypes  = (const int*)  d_in[5];
    const float* emb     = (const float*)d_in[6];
    const float* W1      = (const float*)d_in[7];
    const float* W1_loop = (const float*)d_in[8];
    const float* b1      = (const float*)d_in[9];
    const float* W2      = (const float*)d_in[10];
    const float* W2_loop = (const float*)d_in[11];
    const float* b2      = (const float*)d_in[12];
    const float* A1      = (const float*)d_in[13];
    const float* A2      = (const float*)d_in[14];
    float*       out     = (float*)d_out;

    float *base, *T, *h, *upd, *selin, *hid;
    cudaGetSymbolAddress((void**)&base,  g_base);
    cudaGetSymbolAddress((void**)&T,     g_T);
    cudaGetSymbolAddress((void**)&h,     g_h);
    cudaGetSymbolAddress((void**)&upd,   g_upd);
    cudaGetSymbolAddress((void**)&selin, g_selin);
    cudaGetSymbolAddress((void**)&hid,   g_hid);

    const long long sW = (long long)DIMF * DIMF;        // 65536
    const long long sT = (long long)NN * DIMF;          // per-relation T stride

    // 1) base = emb[node_ids]
    {
        int total = NN * (DIMF / 4);
        gather_base_kernel<<<(total + 255) / 256, 256>>>(emb, nids);
    }

    dim3 gT(DIMF / 64, (NN + 63) / 64, NRELS);     // (4, 782, 8)
    dim3 gL(DIMF / 64, (NN + 63) / 64, 1);

    // 2) layer 1
    sgemm_kernel<0><<<gT, 256>>>(base, W1, T, nullptr, NN, DIMF, DIMF, sW, sT);
    sgemm_kernel<0><<<gL, 256>>>(base, W1_loop, h, b1, NN, DIMF, DIMF, 0, 0);
    edge_scatter_kernel<<<(NE + 3) / 4, 256>>>(src, dst, etypes, T, h);
    relu_kernel<<<(NN * DIMF / 4 + 255) / 256, 256>>>(h, NN * DIMF / 4);

    // 3) layer 2 (no relu)
    sgemm_kernel<0><<<gT, 256>>>(h, W2, T, nullptr, NN, DIMF, DIMF, sW, sT);
    sgemm_kernel<0><<<gL, 256>>>(h, W2_loop, upd, b2, NN, DIMF, DIMF, 0, 0);
    edge_scatter_kernel<<<(NE + 3) / 4, 256>>>(src, dst, etypes, T, upd);

    // 4) adapter on 1632 selected rows
    {
        int total = NSEL * (2 * DIMF / 4);
        sel_gather_kernel<<<(total + 255) / 256, 256>>>(qidx, eidx);
    }
    {
        dim3 g1(ADAPTD / 64, (NSEL + 63) / 64, 1);   // (16, 26)
        sgemm_kernel<2><<<g1, 256>>>(selin, A1, hid, nullptr,
                                     NSEL, ADAPTD, 2 * DIMF, 0, 0);
        dim3 g2(OUTD / 64, (NSEL + 63) / 64, 1);     // (64, 26)
        sgemm_kernel<0><<<g2, 256>>>(hid, A2, out, nullptr,
                                     NSEL, OUTD, ADAPTD, 0, 0);
    }
}